// round 5
// baseline (speedup 1.0000x reference)
#include <cuda_runtime.h>
#include <cstdint>

// KoopmanOperator: y_{t+1} = R(p(y_t)) applied 256 times to y_0 = x[:,0,:]
//   h = tanh(y @ W1^T + b1);  p = h @ W2^T + b2
//   mu = p[2i], om = p[2i+1]; e=exp(dt mu), c=cos(dt om), s=sin(dt om)
//   y'[2i]   = e*(c*y[2i] - s*y[2i+1])
//   y'[2i+1] = e*(s*y[2i] - c*y[2i+1])      (note: minus c*y1, per reference)
// out[b,t,:] = y after step t+1. fp32 throughout, FFMA2 (f32x2) math.

#define D 64
#define T_STEPS 256
#define ROWS_PER_CTA 32
#define THREADS 128
#define STRIDE 68                      // padded row stride (floats), 16B-aligned, conflict-tuned
#define W_FLOATS (64 * STRIDE)         // 4352
#define S_FLOATS (ROWS_PER_CTA * STRIDE) // 2176
#define SMEM_FLOATS (2 * W_FLOATS + 3 * S_FLOATS)
#define DT 0.01f

__device__ __forceinline__ void fma2(unsigned long long& d,
                                     unsigned long long a,
                                     unsigned long long b) {
    asm("fma.rn.f32x2 %0, %1, %2, %0;" : "+l"(d) : "l"(a), "l"(b));
}

__device__ __forceinline__ unsigned long long pack2(float x, float y) {
    unsigned long long u;
    asm("mov.b64 %0, {%1, %2};" : "=l"(u) : "f"(x), "f"(y));
    return u;
}

__device__ __forceinline__ float2 unpack2(unsigned long long u) {
    float2 f;
    asm("mov.b64 {%0, %1}, %2;" : "=f"(f.x), "=f"(f.y) : "l"(u));
    return f;
}

// Accurate fast tanh: ~1e-6 rel error (EX2 + RCP), safe over 256 recurrent steps.
__device__ __forceinline__ float tanh_acc(float x) {
    float ax = fabsf(x);
    float e  = __expf(-2.0f * ax);           // (0, 1]
    float t  = __fdividef(1.0f - e, 1.0f + e);
    return copysignf(t, x);
}

// One GEMV phase for the whole CTA:
//   dst[r][j] = (TANH? tanh : id)( sum_k Ws[j][k]*src[r][k] + bias[j] )
// Thread tile: 4 rows (rg, rg+8, rg+16, rg+24... actually rg + 8*rr) x 4 cols (jb + 16*jj),
// k-paired f32x2 accumulators. Smem layouts padded to STRIDE for conflict-free vector loads.
template <bool TANH>
__device__ __forceinline__ void gemv_phase(const float* __restrict__ Ws,
                                           const float* __restrict__ src,
                                           float* __restrict__ dst,
                                           const float bias[4],
                                           int jb, const int rrow[4]) {
    unsigned long long acc[4][4];
#pragma unroll
    for (int jj = 0; jj < 4; jj++)
#pragma unroll
        for (int rr = 0; rr < 4; rr++)
            acc[jj][rr] = pack2(bias[jj], 0.0f);   // bias folded into even-lane partial

#pragma unroll
    for (int kc = 0; kc < D; kc += 4) {
        unsigned long long ylo[4], yhi[4], wlo[4], whi[4];
#pragma unroll
        for (int rr = 0; rr < 4; rr++) {
            ulonglong2 v = *reinterpret_cast<const ulonglong2*>(src + rrow[rr] * STRIDE + kc);
            ylo[rr] = v.x; yhi[rr] = v.y;
        }
#pragma unroll
        for (int jj = 0; jj < 4; jj++) {
            ulonglong2 v = *reinterpret_cast<const ulonglong2*>(Ws + (jb + 16 * jj) * STRIDE + kc);
            wlo[jj] = v.x; whi[jj] = v.y;
        }
#pragma unroll
        for (int jj = 0; jj < 4; jj++)
#pragma unroll
            for (int rr = 0; rr < 4; rr++) {
                fma2(acc[jj][rr], wlo[jj], ylo[rr]);
                fma2(acc[jj][rr], whi[jj], yhi[rr]);
            }
    }

#pragma unroll
    for (int jj = 0; jj < 4; jj++)
#pragma unroll
        for (int rr = 0; rr < 4; rr++) {
            float2 v = unpack2(acc[jj][rr]);
            float sum = v.x + v.y;
            if (TANH) sum = tanh_acc(sum);
            dst[rrow[rr] * STRIDE + (jb + 16 * jj)] = sum;
        }
}

__global__ void __launch_bounds__(THREADS, 1)
koopman_kernel(const float* __restrict__ x,
               const float* __restrict__ W1g,
               const float* __restrict__ b1g,
               const float* __restrict__ W2g,
               const float* __restrict__ b2g,
               float* __restrict__ out) {
    extern __shared__ float sm[];
    float* W1s = sm;                       // [64][STRIDE]
    float* W2s = sm + W_FLOATS;            // [64][STRIDE]
    float* Ys  = sm + 2 * W_FLOATS;        // [32][STRIDE]  state
    float* Hs  = Ys + S_FLOATS;            // [32][STRIDE]  hidden
    float* Ps  = Hs + S_FLOATS;            // [32][STRIDE]  pre-update

    const int tid = threadIdx.x;
    const int jb  = tid & 15;              // 16 column-blocks
    const int rg  = tid >> 4;              // 8 row-groups
    const int rowbase = blockIdx.x * ROWS_PER_CTA;

    int rrow[4];
#pragma unroll
    for (int rr = 0; rr < 4; rr++) rrow[rr] = rg + 8 * rr;

    // ---- one-time loads: weights -> smem (padded), y0 = x[:,0,:] -> smem ----
    for (int i = tid; i < D * D; i += THREADS) {
        int j = i >> 6, k = i & 63;
        W1s[j * STRIDE + k] = W1g[i];
        W2s[j * STRIDE + k] = W2g[i];
    }
    for (int i = tid; i < ROWS_PER_CTA * D; i += THREADS) {
        int r = i >> 6, k = i & 63;
        Ys[r * STRIDE + k] = x[(size_t)(rowbase + r) * (T_STEPS * D) + k];
    }
    float bias1[4], bias2[4];
#pragma unroll
    for (int jj = 0; jj < 4; jj++) {
        bias1[jj] = b1g[jb + 16 * jj];
        bias2[jj] = b2g[jb + 16 * jj];
    }
    __syncthreads();

    // ---- 256 sequential steps, fully inside one kernel (rows are independent) ----
    for (int t = 0; t < T_STEPS; t++) {
        gemv_phase<true >(W1s, Ys, Hs, bias1, jb, rrow);   // H = tanh(W1 y + b1)
        __syncthreads();
        gemv_phase<false>(W2s, Hs, Ps, bias2, jb, rrow);   // P = W2 h + b2
        __syncthreads();

        // Update phase: thread owns pairs i in {jb, jb+16} for its 4 rows.
        // Each (row, pair) is read+written by exactly one thread -> no races.
#pragma unroll
        for (int rr = 0; rr < 4; rr++) {
            const int row = rrow[rr];
            const size_t ob = ((size_t)(rowbase + row) * T_STEPS + t) * D;
#pragma unroll
            for (int ih = 0; ih < 2; ih++) {
                const int i2 = (jb + 16 * ih) * 2;
                float2 p = *reinterpret_cast<const float2*>(Ps + row * STRIDE + i2);
                float2 y = *reinterpret_cast<const float2*>(Ys + row * STRIDE + i2);
                float e = __expf(DT * p.x);
                float s, c;
                __sincosf(DT * p.y, &s, &c);
                float n0 = e * (c * y.x - s * y.y);
                float n1 = e * (s * y.x - c * y.y);   // reference uses  s*y0 - c*y1
                float2 n = make_float2(n0, n1);
                *reinterpret_cast<float2*>(Ys + row * STRIDE + i2) = n;
                *reinterpret_cast<float2*>(out + ob + i2) = n;
            }
        }
        __syncthreads();
    }
}

extern "C" void kernel_launch(void* const* d_in, const int* in_sizes, int n_in,
                              void* d_out, int out_size) {
    const float* x  = (const float*)d_in[0];
    const float* W1 = (const float*)d_in[1];
    const float* b1 = (const float*)d_in[2];
    const float* W2 = (const float*)d_in[3];
    const float* b2 = (const float*)d_in[4];
    float* out = (float*)d_out;

    const int smem_bytes = SMEM_FLOATS * (int)sizeof(float);   // 60928 B
    cudaFuncSetAttribute(koopman_kernel,
                         cudaFuncAttributeMaxDynamicSharedMemorySize, smem_bytes);

    // 4096 rows / 32 per CTA = 128 CTAs; one launch runs all 256 steps.
    koopman_kernel<<<128, THREADS, smem_bytes>>>(x, W1, b1, W2, b2, out);
}

// round 6
// speedup vs baseline: 1.0009x; 1.0009x over previous
#include <cuda_runtime.h>
#include <cstdint>

// KoopmanOperator: y_{t+1} = R(p(y_t)) applied 256 times to y_0 = x[:,0,:]
//   h = tanh(y @ W1^T + b1);  p = h @ W2^T + b2
//   mu = p[2i], om = p[2i+1]; e=exp(dt mu), c=cos(dt om), s=sin(dt om)
//   y'[2i]   = e*(c*y[2i] - s*y[2i+1])
//   y'[2i+1] = e*(s*y[2i] - c*y[2i+1])      (note: minus c*y1, per reference)
// out[b,t,:] = y after step t+1. fp32 throughout, FFMA2 (f32x2) math.

#define D 64
#define T_STEPS 256
#define ROWS_PER_CTA 32
#define THREADS 128
#define STRIDE 68                      // padded row stride (floats), 16B-aligned, conflict-tuned
#define W_FLOATS (64 * STRIDE)         // 4352
#define S_FLOATS (ROWS_PER_CTA * STRIDE) // 2176
#define SMEM_FLOATS (2 * W_FLOATS + 3 * S_FLOATS)
#define DT 0.01f

__device__ __forceinline__ void fma2(unsigned long long& d,
                                     unsigned long long a,
                                     unsigned long long b) {
    asm("fma.rn.f32x2 %0, %1, %2, %0;" : "+l"(d) : "l"(a), "l"(b));
}

__device__ __forceinline__ unsigned long long pack2(float x, float y) {
    unsigned long long u;
    asm("mov.b64 %0, {%1, %2};" : "=l"(u) : "f"(x), "f"(y));
    return u;
}

__device__ __forceinline__ float2 unpack2(unsigned long long u) {
    float2 f;
    asm("mov.b64 {%0, %1}, %2;" : "=f"(f.x), "=f"(f.y) : "l"(u));
    return f;
}

// Accurate fast tanh: ~1e-6 rel error (EX2 + RCP), safe over 256 recurrent steps.
__device__ __forceinline__ float tanh_acc(float x) {
    float ax = fabsf(x);
    float e  = __expf(-2.0f * ax);           // (0, 1]
    float t  = __fdividef(1.0f - e, 1.0f + e);
    return copysignf(t, x);
}

// One GEMV phase for the whole CTA:
//   dst[r][j] = (TANH? tanh : id)( sum_k Ws[j][k]*src[r][k] + bias[j] )
// Thread tile: 4 rows (rg, rg+8, rg+16, rg+24... actually rg + 8*rr) x 4 cols (jb + 16*jj),
// k-paired f32x2 accumulators. Smem layouts padded to STRIDE for conflict-free vector loads.
template <bool TANH>
__device__ __forceinline__ void gemv_phase(const float* __restrict__ Ws,
                                           const float* __restrict__ src,
                                           float* __restrict__ dst,
                                           const float bias[4],
                                           int jb, const int rrow[4]) {
    unsigned long long acc[4][4];
#pragma unroll
    for (int jj = 0; jj < 4; jj++)
#pragma unroll
        for (int rr = 0; rr < 4; rr++)
            acc[jj][rr] = pack2(bias[jj], 0.0f);   // bias folded into even-lane partial

#pragma unroll
    for (int kc = 0; kc < D; kc += 4) {
        unsigned long long ylo[4], yhi[4], wlo[4], whi[4];
#pragma unroll
        for (int rr = 0; rr < 4; rr++) {
            ulonglong2 v = *reinterpret_cast<const ulonglong2*>(src + rrow[rr] * STRIDE + kc);
            ylo[rr] = v.x; yhi[rr] = v.y;
        }
#pragma unroll
        for (int jj = 0; jj < 4; jj++) {
            ulonglong2 v = *reinterpret_cast<const ulonglong2*>(Ws + (jb + 16 * jj) * STRIDE + kc);
            wlo[jj] = v.x; whi[jj] = v.y;
        }
#pragma unroll
        for (int jj = 0; jj < 4; jj++)
#pragma unroll
            for (int rr = 0; rr < 4; rr++) {
                fma2(acc[jj][rr], wlo[jj], ylo[rr]);
                fma2(acc[jj][rr], whi[jj], yhi[rr]);
            }
    }

#pragma unroll
    for (int jj = 0; jj < 4; jj++)
#pragma unroll
        for (int rr = 0; rr < 4; rr++) {
            float2 v = unpack2(acc[jj][rr]);
            float sum = v.x + v.y;
            if (TANH) sum = tanh_acc(sum);
            dst[rrow[rr] * STRIDE + (jb + 16 * jj)] = sum;
        }
}

__global__ void __launch_bounds__(THREADS, 1)
koopman_kernel(const float* __restrict__ x,
               const float* __restrict__ W1g,
               const float* __restrict__ b1g,
               const float* __restrict__ W2g,
               const float* __restrict__ b2g,
               float* __restrict__ out) {
    extern __shared__ float sm[];
    float* W1s = sm;                       // [64][STRIDE]
    float* W2s = sm + W_FLOATS;            // [64][STRIDE]
    float* Ys  = sm + 2 * W_FLOATS;        // [32][STRIDE]  state
    float* Hs  = Ys + S_FLOATS;            // [32][STRIDE]  hidden
    float* Ps  = Hs + S_FLOATS;            // [32][STRIDE]  pre-update

    const int tid = threadIdx.x;
    const int jb  = tid & 15;              // 16 column-blocks
    const int rg  = tid >> 4;              // 8 row-groups
    const int rowbase = blockIdx.x * ROWS_PER_CTA;

    int rrow[4];
#pragma unroll
    for (int rr = 0; rr < 4; rr++) rrow[rr] = rg + 8 * rr;

    // ---- one-time loads: weights -> smem (padded), y0 = x[:,0,:] -> smem ----
    for (int i = tid; i < D * D; i += THREADS) {
        int j = i >> 6, k = i & 63;
        W1s[j * STRIDE + k] = W1g[i];
        W2s[j * STRIDE + k] = W2g[i];
    }
    for (int i = tid; i < ROWS_PER_CTA * D; i += THREADS) {
        int r = i >> 6, k = i & 63;
        Ys[r * STRIDE + k] = x[(size_t)(rowbase + r) * (T_STEPS * D) + k];
    }
    float bias1[4], bias2[4];
#pragma unroll
    for (int jj = 0; jj < 4; jj++) {
        bias1[jj] = b1g[jb + 16 * jj];
        bias2[jj] = b2g[jb + 16 * jj];
    }
    __syncthreads();

    // ---- 256 sequential steps, fully inside one kernel (rows are independent) ----
    for (int t = 0; t < T_STEPS; t++) {
        gemv_phase<true >(W1s, Ys, Hs, bias1, jb, rrow);   // H = tanh(W1 y + b1)
        __syncthreads();
        gemv_phase<false>(W2s, Hs, Ps, bias2, jb, rrow);   // P = W2 h + b2
        __syncthreads();

        // Update phase: thread owns pairs i in {jb, jb+16} for its 4 rows.
        // Each (row, pair) is read+written by exactly one thread -> no races.
#pragma unroll
        for (int rr = 0; rr < 4; rr++) {
            const int row = rrow[rr];
            const size_t ob = ((size_t)(rowbase + row) * T_STEPS + t) * D;
#pragma unroll
            for (int ih = 0; ih < 2; ih++) {
                const int i2 = (jb + 16 * ih) * 2;
                float2 p = *reinterpret_cast<const float2*>(Ps + row * STRIDE + i2);
                float2 y = *reinterpret_cast<const float2*>(Ys + row * STRIDE + i2);
                float e = __expf(DT * p.x);
                float s, c;
                __sincosf(DT * p.y, &s, &c);
                float n0 = e * (c * y.x - s * y.y);
                float n1 = e * (s * y.x - c * y.y);   // reference uses  s*y0 - c*y1
                float2 n = make_float2(n0, n1);
                *reinterpret_cast<float2*>(Ys + row * STRIDE + i2) = n;
                *reinterpret_cast<float2*>(out + ob + i2) = n;
            }
        }
        __syncthreads();
    }
}

extern "C" void kernel_launch(void* const* d_in, const int* in_sizes, int n_in,
                              void* d_out, int out_size) {
    const float* x  = (const float*)d_in[0];
    const float* W1 = (const float*)d_in[1];
    const float* b1 = (const float*)d_in[2];
    const float* W2 = (const float*)d_in[3];
    const float* b2 = (const float*)d_in[4];
    float* out = (float*)d_out;

    const int smem_bytes = SMEM_FLOATS * (int)sizeof(float);   // 60928 B
    cudaFuncSetAttribute(koopman_kernel,
                         cudaFuncAttributeMaxDynamicSharedMemorySize, smem_bytes);

    // 4096 rows / 32 per CTA = 128 CTAs; one launch runs all 256 steps.
    koopman_kernel<<<128, THREADS, smem_bytes>>>(x, W1, b1, W2, b2, out);
}

// round 7
// speedup vs baseline: 1.0037x; 1.0028x over previous
#include <cuda_runtime.h>
#include <cstdint>

// KoopmanOperator: y_{t+1} = R(p(y_t)) applied 256 times to y_0 = x[:,0,:]
//   h = tanh(y @ W1^T + b1);  p = h @ W2^T + b2
//   mu = p[2i], om = p[2i+1]; e=exp(dt mu), c=cos(dt om), s=sin(dt om)
//   y'[2i]   = e*(c*y[2i] - s*y[2i+1])
//   y'[2i+1] = e*(s*y[2i] - c*y[2i+1])      (note: minus c*y1, per reference)
// out[b,t,:] = y after step t+1. fp32 throughout, FFMA2 (f32x2) math.

#define D 64
#define T_STEPS 256
#define ROWS_PER_CTA 32
#define THREADS 128
#define STRIDE 68                      // padded row stride (floats), 16B-aligned, conflict-tuned
#define W_FLOATS (64 * STRIDE)         // 4352
#define S_FLOATS (ROWS_PER_CTA * STRIDE) // 2176
#define SMEM_FLOATS (2 * W_FLOATS + 3 * S_FLOATS)
#define DT 0.01f

__device__ __forceinline__ void fma2(unsigned long long& d,
                                     unsigned long long a,
                                     unsigned long long b) {
    asm("fma.rn.f32x2 %0, %1, %2, %0;" : "+l"(d) : "l"(a), "l"(b));
}

__device__ __forceinline__ unsigned long long pack2(float x, float y) {
    unsigned long long u;
    asm("mov.b64 %0, {%1, %2};" : "=l"(u) : "f"(x), "f"(y));
    return u;
}

__device__ __forceinline__ float2 unpack2(unsigned long long u) {
    float2 f;
    asm("mov.b64 {%0, %1}, %2;" : "=f"(f.x), "=f"(f.y) : "l"(u));
    return f;
}

// Accurate fast tanh: ~1e-6 rel error (EX2 + RCP), safe over 256 recurrent steps.
__device__ __forceinline__ float tanh_acc(float x) {
    float ax = fabsf(x);
    float e  = __expf(-2.0f * ax);           // (0, 1]
    float t  = __fdividef(1.0f - e, 1.0f + e);
    return copysignf(t, x);
}

// One GEMV phase for the whole CTA:
//   dst[r][j] = (TANH? tanh : id)( sum_k Ws[j][k]*src[r][k] + bias[j] )
// Thread tile: 4 rows (rg, rg+8, rg+16, rg+24... actually rg + 8*rr) x 4 cols (jb + 16*jj),
// k-paired f32x2 accumulators. Smem layouts padded to STRIDE for conflict-free vector loads.
template <bool TANH>
__device__ __forceinline__ void gemv_phase(const float* __restrict__ Ws,
                                           const float* __restrict__ src,
                                           float* __restrict__ dst,
                                           const float bias[4],
                                           int jb, const int rrow[4]) {
    unsigned long long acc[4][4];
#pragma unroll
    for (int jj = 0; jj < 4; jj++)
#pragma unroll
        for (int rr = 0; rr < 4; rr++)
            acc[jj][rr] = pack2(bias[jj], 0.0f);   // bias folded into even-lane partial

#pragma unroll
    for (int kc = 0; kc < D; kc += 4) {
        unsigned long long ylo[4], yhi[4], wlo[4], whi[4];
#pragma unroll
        for (int rr = 0; rr < 4; rr++) {
            ulonglong2 v = *reinterpret_cast<const ulonglong2*>(src + rrow[rr] * STRIDE + kc);
            ylo[rr] = v.x; yhi[rr] = v.y;
        }
#pragma unroll
        for (int jj = 0; jj < 4; jj++) {
            ulonglong2 v = *reinterpret_cast<const ulonglong2*>(Ws + (jb + 16 * jj) * STRIDE + kc);
            wlo[jj] = v.x; whi[jj] = v.y;
        }
#pragma unroll
        for (int jj = 0; jj < 4; jj++)
#pragma unroll
            for (int rr = 0; rr < 4; rr++) {
                fma2(acc[jj][rr], wlo[jj], ylo[rr]);
                fma2(acc[jj][rr], whi[jj], yhi[rr]);
            }
    }

#pragma unroll
    for (int jj = 0; jj < 4; jj++)
#pragma unroll
        for (int rr = 0; rr < 4; rr++) {
            float2 v = unpack2(acc[jj][rr]);
            float sum = v.x + v.y;
            if (TANH) sum = tanh_acc(sum);
            dst[rrow[rr] * STRIDE + (jb + 16 * jj)] = sum;
        }
}

__global__ void __launch_bounds__(THREADS, 1)
koopman_kernel(const float* __restrict__ x,
               const float* __restrict__ W1g,
               const float* __restrict__ b1g,
               const float* __restrict__ W2g,
               const float* __restrict__ b2g,
               float* __restrict__ out) {
    extern __shared__ float sm[];
    float* W1s = sm;                       // [64][STRIDE]
    float* W2s = sm + W_FLOATS;            // [64][STRIDE]
    float* Ys  = sm + 2 * W_FLOATS;        // [32][STRIDE]  state
    float* Hs  = Ys + S_FLOATS;            // [32][STRIDE]  hidden
    float* Ps  = Hs + S_FLOATS;            // [32][STRIDE]  pre-update

    const int tid = threadIdx.x;
    const int jb  = tid & 15;              // 16 column-blocks
    const int rg  = tid >> 4;              // 8 row-groups
    const int rowbase = blockIdx.x * ROWS_PER_CTA;

    int rrow[4];
#pragma unroll
    for (int rr = 0; rr < 4; rr++) rrow[rr] = rg + 8 * rr;

    // ---- one-time loads: weights -> smem (padded), y0 = x[:,0,:] -> smem ----
    for (int i = tid; i < D * D; i += THREADS) {
        int j = i >> 6, k = i & 63;
        W1s[j * STRIDE + k] = W1g[i];
        W2s[j * STRIDE + k] = W2g[i];
    }
    for (int i = tid; i < ROWS_PER_CTA * D; i += THREADS) {
        int r = i >> 6, k = i & 63;
        Ys[r * STRIDE + k] = x[(size_t)(rowbase + r) * (T_STEPS * D) + k];
    }
    float bias1[4], bias2[4];
#pragma unroll
    for (int jj = 0; jj < 4; jj++) {
        bias1[jj] = b1g[jb + 16 * jj];
        bias2[jj] = b2g[jb + 16 * jj];
    }
    __syncthreads();

    // ---- 256 sequential steps, fully inside one kernel (rows are independent) ----
    for (int t = 0; t < T_STEPS; t++) {
        gemv_phase<true >(W1s, Ys, Hs, bias1, jb, rrow);   // H = tanh(W1 y + b1)
        __syncthreads();
        gemv_phase<false>(W2s, Hs, Ps, bias2, jb, rrow);   // P = W2 h + b2
        __syncthreads();

        // Update phase: thread owns pairs i in {jb, jb+16} for its 4 rows.
        // Each (row, pair) is read+written by exactly one thread -> no races.
#pragma unroll
        for (int rr = 0; rr < 4; rr++) {
            const int row = rrow[rr];
            const size_t ob = ((size_t)(rowbase + row) * T_STEPS + t) * D;
#pragma unroll
            for (int ih = 0; ih < 2; ih++) {
                const int i2 = (jb + 16 * ih) * 2;
                float2 p = *reinterpret_cast<const float2*>(Ps + row * STRIDE + i2);
                float2 y = *reinterpret_cast<const float2*>(Ys + row * STRIDE + i2);
                float e = __expf(DT * p.x);
                float s, c;
                __sincosf(DT * p.y, &s, &c);
                float n0 = e * (c * y.x - s * y.y);
                float n1 = e * (s * y.x - c * y.y);   // reference uses  s*y0 - c*y1
                float2 n = make_float2(n0, n1);
                *reinterpret_cast<float2*>(Ys + row * STRIDE + i2) = n;
                *reinterpret_cast<float2*>(out + ob + i2) = n;
            }
        }
        __syncthreads();
    }
}

extern "C" void kernel_launch(void* const* d_in, const int* in_sizes, int n_in,
                              void* d_out, int out_size) {
    const float* x  = (const float*)d_in[0];
    const float* W1 = (const float*)d_in[1];
    const float* b1 = (const float*)d_in[2];
    const float* W2 = (const float*)d_in[3];
    const float* b2 = (const float*)d_in[4];
    float* out = (float*)d_out;

    const int smem_bytes = SMEM_FLOATS * (int)sizeof(float);   // 60928 B
    cudaFuncSetAttribute(koopman_kernel,
                         cudaFuncAttributeMaxDynamicSharedMemorySize, smem_bytes);

    // 4096 rows / 32 per CTA = 128 CTAs; one launch runs all 256 steps.
    koopman_kernel<<<128, THREADS, smem_bytes>>>(x, W1, b1, W2, b2, out);
}